// round 16
// baseline (speedup 1.0000x reference)
#include <cuda_runtime.h>
#include <cuda_fp16.h>
#include <cstdint>

// ElementUpdate: out[n,:] = h_prev[n,:] + W[z[n]] @ m_curr[n,:]
// N=16384, D=128, S=119, z sorted.
// R16: single persistent kernel. 128 co-resident CTAs: each converts a W slice
// to fp16, device-wide sense-reversing barrier, then processes 2 tiles
// (bid, bid+128) through one unified cp.async W job pipeline (ring of 2
// buffers, j+2 lookahead crossing the tile boundary). A tiles + scans for both
// tiles are done pre-barrier to overlap the conversion.

static constexpr int D = 128;
static constexpr int NSPEC = 119;
static constexpr int TILE_M = 64;
static constexpr int NT = 256;
static constexpr int NCTA = 128;
static constexpr int HPAD = 136;               // half stride, conflict-free
static constexpr int HDR = 4096;
static constexpr int A_BYTES = TILE_M * HPAD * 2;   // 17408
static constexpr int W_BYTES = D * HPAD * 2;        // 34816
static constexpr int SMEM_BYTES = HDR + 2 * A_BYTES + 2 * W_BYTES;  // 108544

__device__ __half g_wh[NSPEC * D * D];
__device__ unsigned g_cnt = 0;
__device__ volatile unsigned g_gen = 0;

__device__ __forceinline__ uint32_t pack_h2(float lo, float hi) {
    uint32_t r;
    asm("cvt.rn.f16x2.f32 %0, %1, %2;" : "=r"(r) : "f"(hi), "f"(lo));
    return r;
}

__device__ __forceinline__ uint32_t smem_u32(const void* p) {
    uint32_t a;
    asm("{ .reg .u64 t; cvta.to.shared.u64 t, %1; cvt.u32.u64 %0, t; }" : "=r"(a) : "l"(p));
    return a;
}

__device__ __forceinline__ void cpa16(uint32_t dst, const void* src) {
    asm volatile("cp.async.cg.shared.global [%0], [%1], 16;" :: "r"(dst), "l"(src));
}
#define CP_COMMIT() asm volatile("cp.async.commit_group;" ::: "memory")
#define CP_WAIT(n)  asm volatile("cp.async.wait_group %0;" :: "n"(n) : "memory")

__device__ __forceinline__ void mma_f16(float* d, const uint32_t* a,
                                        uint32_t b0, uint32_t b1) {
    asm volatile(
        "mma.sync.aligned.m16n8k16.row.col.f32.f16.f16.f32 "
        "{%0,%1,%2,%3}, {%4,%5,%6,%7}, {%8,%9}, {%0,%1,%2,%3};"
        : "+f"(d[0]), "+f"(d[1]), "+f"(d[2]), "+f"(d[3])
        : "r"(a[0]), "r"(a[1]), "r"(a[2]), "r"(a[3]), "r"(b0), "r"(b1));
}

__global__ void __launch_bounds__(NT, 1)
element_update_kernel(const float* __restrict__ h_prev,
                      const float* __restrict__ m_curr,
                      const int* __restrict__ atom_types,
                      const float* __restrict__ weight,
                      float* __restrict__ out) {
    extern __shared__ __align__(16) char smem[];
    const int tid = threadIdx.x;
    const int lane = tid & 31;
    const int wid = tid >> 5;
    const int bid = blockIdx.x;

    int* sCnt   = (int*)(smem + 0);
    int* sNseg  = (int*)(smem + 32);       // [2]
    int* sRowA[2]  = {(int*)(smem + 64),  (int*)(smem + 352)};   // 65 ints each
    int* sSpecA[2] = {(int*)(smem + 704), (int*)(smem + 992)};   // 64 ints each
    __half* sA[2] = {(__half*)(smem + HDR), (__half*)(smem + HDR + A_BYTES)};
    __half* sW0 = (__half*)(smem + HDR + 2 * A_BYTES);
    __half* sW1 = (__half*)(smem + HDR + 2 * A_BYTES + W_BYTES);

    const uint32_t sbase = smem_u32(smem);
    const uint32_t wU0 = sbase + HDR + 2 * A_BYTES;
    const uint32_t wU1 = wU0 + W_BYTES;

    // ---- phase 1: convert this CTA's W slice fp32 -> fp16 ----
    {
        const float4* src = (const float4*)weight;
        const int total = NSPEC * D * D / 4;               // 487424
        for (int i = bid * NT + tid; i < total; i += NCTA * NT) {
            float4 v = src[i];
            uint2 u;
            u.x = pack_h2(v.x, v.y);
            u.y = pack_h2(v.z, v.w);
            ((uint2*)g_wh)[i] = u;
        }
    }

    // ---- phase 2 (pre-barrier, overlaps conversion): A fills + scans x2 ----
    const int R[2] = {bid * TILE_M, (bid + NCTA) * TILE_M};
    #pragma unroll
    for (int t = 0; t < 2; t++) {
        __half* A = sA[t];
        #pragma unroll
        for (int j = 0; j < 8; j++) {
            int i = tid + j * NT;
            int r = i >> 5, c4 = (i & 31) << 2;
            float4 v = *(const float4*)(m_curr + (size_t)(R[t] + r) * D + c4);
            uint2 u;
            u.x = pack_h2(v.x, v.y);
            u.y = pack_h2(v.z, v.w);
            *(uint2*)(A + r * HPAD + c4) = u;
        }
    }
    for (int t = 0; t < 2; t++) {
        int* sRow = sRowA[t];
        int* sSpec = sSpecA[t];
        bool bd = false; int wpre = 0, zr = 0;
        if (tid < TILE_M) {
            zr = atom_types[R[t] + tid];
            int zp = (tid == 0) ? -1 : atom_types[R[t] + tid - 1];
            bd = (zp != zr);
            unsigned msk = __ballot_sync(0xffffffffu, bd);
            wpre = __popc(msk & ((1u << lane) - 1u));
            if (lane == 0) sCnt[wid] = __popc(msk);
        }
        __syncthreads();
        if (tid == 0) {
            int c0 = sCnt[0], c1 = sCnt[1];
            sCnt[2] = c0;
            sNseg[t] = c0 + c1;
            sRow[c0 + c1] = TILE_M;
        }
        __syncthreads();
        if (tid < TILE_M && bd) {
            int i = (wid ? sCnt[2] : 0) + wpre;
            sRow[i] = tid;
            sSpec[i] = zr;
        }
        __syncthreads();
    }
    const int nseg0 = sNseg[0];
    const int K = nseg0 + sNseg[1];

    // ---- phase 3: device-wide barrier (all 128 CTAs co-resident) ----
    if (tid == 0) {
        __threadfence();
        unsigned gen = g_gen;
        unsigned old = atomicAdd(&g_cnt, 1u);
        if (old == NCTA - 1) {
            g_cnt = 0;
            __threadfence();
            g_gen = gen + 1u;
        } else {
            while (g_gen == gen) { __nanosleep(64); }
        }
        __threadfence();
    }
    __syncthreads();

    // ---- phase 4: unified W job pipeline over both tiles ----
    auto jobSpec = [&](int j) {
        return (j < nseg0) ? sSpecA[0][j] : sSpecA[1][j - nseg0];
    };
    auto issue_w = [&](int s, int parity) {
        const __half* src = g_wh + (size_t)s * (D * D);
        uint32_t dU = parity ? wU1 : wU0;
        #pragma unroll
        for (int j = 0; j < 8; j++) {
            int i = tid + j * NT;
            int r = i >> 4, c8 = (i & 15) << 3;
            cpa16(dU + (uint32_t)(r * HPAD + c8) * 2u, src + r * D + c8);
        }
        CP_COMMIT();
    };

    issue_w(jobSpec(0), 0);
    if (K > 1) issue_w(jobSpec(1), 1);

    const int wr = wid >> 1;     // 0..3
    const int wc = wid & 1;      // 0..1
    const int rlo = wr * 16;
    const int lr = lane >> 2;    // 0..7
    const int lc = lane & 3;     // 0..3
    const int bOff = (wc * 64 + lr) * HPAD + lc * 2;

    float acc[8][4];
    #pragma unroll
    for (int nt = 0; nt < 8; nt++)
        #pragma unroll
        for (int j = 0; j < 4; j++) acc[nt][j] = 0.f;

    auto epilogue = [&](int t) {
        #pragma unroll
        for (int h = 0; h < 2; h++) {
            const int r = R[t] + rlo + 8 * h + lr;
            const float* hp = h_prev + (size_t)r * D;
            float* op = out + (size_t)r * D;
            #pragma unroll
            for (int nt = 0; nt < 8; nt++) {
                const int c = wc * 64 + 8 * nt + lc * 2;
                float2 hv = *(const float2*)(hp + c);
                float2 o;
                o.x = hv.x + acc[nt][2 * h + 0];
                o.y = hv.y + acc[nt][2 * h + 1];
                *(float2*)(op + c) = o;
            }
        }
    };

    const __half* pA0 = sA[0] + (rlo + lr) * HPAD + lc * 2;
    const __half* pA1 = pA0 + 8 * HPAD;

    for (int j = 0; j < K; j++) {
        if (j == nseg0) {                 // tile boundary (nseg0 >= 1)
            epilogue(0);
            #pragma unroll
            for (int nt = 0; nt < 8; nt++)
                #pragma unroll
                for (int q = 0; q < 4; q++) acc[nt][q] = 0.f;
            pA0 = sA[1] + (rlo + lr) * HPAD + lc * 2;
            pA1 = pA0 + 8 * HPAD;
        }
        if (j + 1 < K) { CP_WAIT(1); } else { CP_WAIT(0); }
        __syncthreads();

        const int k = (j < nseg0) ? j : j - nseg0;
        const int* sRow = (j < nseg0) ? sRowA[0] : sRowA[1];
        const int a = sRow[k];
        const int b = sRow[k + 1];
        const __half* pB0 = ((j & 1) ? sW1 : sW0) + bOff;

        if (b > rlo && a < rlo + 16) {
            const int r0 = rlo + lr;
            const uint32_t am0 = (r0 >= a && r0 < b) ? 0xffffffffu : 0u;
            const uint32_t am1 = (r0 + 8 >= a && r0 + 8 < b) ? 0xffffffffu : 0u;

            #pragma unroll
            for (int ks = 0; ks < 8; ks++) {
                const int k0 = ks * 16;
                uint32_t aF[4];
                aF[0] = *(const uint32_t*)(pA0 + k0) & am0;
                aF[1] = *(const uint32_t*)(pA1 + k0) & am1;
                aF[2] = *(const uint32_t*)(pA0 + k0 + 8) & am0;
                aF[3] = *(const uint32_t*)(pA1 + k0 + 8) & am1;
                #pragma unroll
                for (int nt = 0; nt < 8; nt++) {
                    const __half* pB = pB0 + nt * (8 * HPAD) + k0;
                    uint32_t b0 = *(const uint32_t*)(pB);
                    uint32_t b1 = *(const uint32_t*)(pB + 8);
                    mma_f16(acc[nt], aF, b0, b1);
                }
            }
        }

        __syncthreads();
        if (j + 2 < K) issue_w(jobSpec(j + 2), j & 1);   // buffer (j+2)&1 == j&1, just freed
    }
    epilogue(1);
}

extern "C" void kernel_launch(void* const* d_in, const int* in_sizes, int n_in,
                              void* d_out, int out_size) {
    const float* h_prev     = (const float*)d_in[0];
    const float* m_curr     = (const float*)d_in[1];
    const int*   atom_types = (const int*)d_in[2];
    const float* weight     = (const float*)d_in[3];
    float* out = (float*)d_out;

    cudaFuncSetAttribute(element_update_kernel,
                         cudaFuncAttributeMaxDynamicSharedMemorySize, SMEM_BYTES);
    element_update_kernel<<<NCTA, NT, SMEM_BYTES>>>(h_prev, m_curr, atom_types,
                                                    weight, out);
}

// round 17
// speedup vs baseline: 1.2737x; 1.2737x over previous
#include <cuda_runtime.h>
#include <cuda_fp16.h>
#include <cstdint>

// ElementUpdate: out[n,:] = h_prev[n,:] + W[z[n]] @ m_curr[n,:]
// N=16384, D=128, S=119, z sorted.
// R17: R15 (cp.async fp16-W pipeline, main 12.4us) tightened to a single
// co-resident wave: W jobs split into k-halves (buffer 128 rows x 64 halves,
// WPAD=72 -> stride 36 words = 4 mod 32, conflict-free) so SMEM = 55KB and
// 3 CTAs/SM => all 256 CTAs resident at once. Both k-half prefetches of
// segment 0 issue before the scan. Prologue converts W to fp16 once.

static constexpr int D = 128;
static constexpr int NSPEC = 119;
static constexpr int TILE_M = 64;
static constexpr int NT = 256;
static constexpr int HPAD = 136;              // A half-stride (68 words = 4 mod 32)
static constexpr int WPAD = 72;               // W half-stride (36 words = 4 mod 32)
static constexpr int HDR = 1024;
static constexpr int A_BYTES = TILE_M * HPAD * 2;   // 17408
static constexpr int W_BYTES = D * WPAD * 2;        // 18432 per k-half buffer
static constexpr int SMEM_BYTES = HDR + A_BYTES + 2 * W_BYTES;  // 55296 -> 3 CTAs/SM

__device__ __half g_wh[NSPEC * D * D];   // fp16 weights (prologue output)

__device__ __forceinline__ uint32_t pack_h2(float lo, float hi) {
    uint32_t r;
    asm("cvt.rn.f16x2.f32 %0, %1, %2;" : "=r"(r) : "f"(hi), "f"(lo));
    return r;
}

__device__ __forceinline__ uint32_t smem_u32(const void* p) {
    uint32_t a;
    asm("{ .reg .u64 t; cvta.to.shared.u64 t, %1; cvt.u32.u64 %0, t; }" : "=r"(a) : "l"(p));
    return a;
}

__device__ __forceinline__ void cpa16(uint32_t dst, const void* src) {
    asm volatile("cp.async.ca.shared.global [%0], [%1], 16;" :: "r"(dst), "l"(src));
}
#define CP_COMMIT() asm volatile("cp.async.commit_group;" ::: "memory")
#define CP_WAIT(n)  asm volatile("cp.async.wait_group %0;" :: "n"(n) : "memory")

__device__ __forceinline__ void mma_f16(float* d, const uint32_t* a,
                                        uint32_t b0, uint32_t b1) {
    asm volatile(
        "mma.sync.aligned.m16n8k16.row.col.f32.f16.f16.f32 "
        "{%0,%1,%2,%3}, {%4,%5,%6,%7}, {%8,%9}, {%0,%1,%2,%3};"
        : "+f"(d[0]), "+f"(d[1]), "+f"(d[2]), "+f"(d[3])
        : "r"(a[0]), "r"(a[1]), "r"(a[2]), "r"(a[3]), "r"(b0), "r"(b1));
}

// ---------------- prologue: weight fp32 -> fp16 ----------------
__global__ void __launch_bounds__(NT, 4) convert_w(const float* __restrict__ w) {
    int i = blockIdx.x * NT + threadIdx.x;            // over float4 chunks
    float4 v = ((const float4*)w)[i];
    uint2 u;
    u.x = pack_h2(v.x, v.y);
    u.y = pack_h2(v.z, v.w);
    ((uint2*)g_wh)[i] = u;
}

// ---------------- main ----------------
__global__ void __launch_bounds__(NT, 3)
element_update_kernel(const float* __restrict__ h_prev,
                      const float* __restrict__ m_curr,
                      const int* __restrict__ atom_types,
                      float* __restrict__ out) {
    extern __shared__ __align__(16) char smem[];
    const int tid = threadIdx.x;
    const int lane = tid & 31;
    const int wid = tid >> 5;
    const int R0 = blockIdx.x * TILE_M;

    int* sCnt  = (int*)(smem + 0);
    int* sNseg = (int*)(smem + 32);
    int* sRow  = (int*)(smem + 64);     // up to TILE_M+1
    int* sSpec = (int*)(smem + 384);    // up to TILE_M
    __half* sA  = (__half*)(smem + HDR);
    __half* sW0 = (__half*)(smem + HDR + A_BYTES);
    __half* sW1 = (__half*)(smem + HDR + A_BYTES + W_BYTES);

    const uint32_t sbase = smem_u32(smem);
    const uint32_t wU0 = sbase + HDR + A_BYTES;
    const uint32_t wU1 = wU0 + W_BYTES;

    // fp16 W[s], k-half kh -> buffer parity. 4 x 16B chunks per thread.
    auto issue_w = [&](int s, int kh, int parity) {
        const __half* src = g_wh + (size_t)s * (D * D) + kh * 64;
        uint32_t dU = parity ? wU1 : wU0;
        #pragma unroll
        for (int j = 0; j < 4; j++) {
            int i = tid + j * NT;
            int r = i >> 3, c8 = (i & 7) << 3;      // 8 x 16B chunks per 64-half row
            cpa16(dU + (uint32_t)(r * WPAD + c8) * 2u, src + r * D + c8);
        }
        CP_COMMIT();
    };

    // s0 LDG first (latency overlapped by the A fill)
    const int s0 = atom_types[R0];

    // ---- A fill: m_curr -> fp16 SMEM ----
    #pragma unroll
    for (int j = 0; j < 8; j++) {
        int i = tid + j * NT;
        int r = i >> 5, c4 = (i & 31) << 2;
        float4 v = *(const float4*)(m_curr + (size_t)(R0 + r) * D + c4);
        uint2 u;
        u.x = pack_h2(v.x, v.y);
        u.y = pack_h2(v.z, v.w);
        *(uint2*)(sA + r * HPAD + c4) = u;
    }

    // ---- both k-half prefetches of segment 0 (only need s0) ----
    issue_w(s0, 0, 0);
    issue_w(s0, 1, 1);

    // ---- species-segment scan over TILE_M sorted z values (warps 0-1) ----
    bool bd = false; int wpre = 0, zr = 0;
    if (tid < TILE_M) {
        zr = atom_types[R0 + tid];
        int zp = (tid == 0) ? -1 : atom_types[R0 + tid - 1];
        bd = (zp != zr);
        unsigned msk = __ballot_sync(0xffffffffu, bd);
        wpre = __popc(msk & ((1u << lane) - 1u));
        if (lane == 0) sCnt[wid] = __popc(msk);
    }
    __syncthreads();
    if (tid == 0) {
        int c0 = sCnt[0], c1 = sCnt[1];
        sCnt[2] = c0;
        *sNseg = c0 + c1;
        sRow[c0 + c1] = TILE_M;
    }
    __syncthreads();
    if (tid < TILE_M && bd) {
        int i = (wid ? sCnt[2] : 0) + wpre;
        sRow[i] = tid;
        sSpec[i] = zr;
    }
    __syncthreads();
    const int nseg = *sNseg;
    const int K = 2 * nseg;                  // jobs: (seg, k-half)

    // ---- warp geometry: rows [16*wr,+16) x cols [64*wc,+64) ----
    const int wr = wid >> 1;     // 0..3
    const int wc = wid & 1;      // 0..1
    const int rlo = wr * 16;
    const int lr = lane >> 2;    // 0..7
    const int lc = lane & 3;     // 0..3

    float acc[8][4];
    #pragma unroll
    for (int nt = 0; nt < 8; nt++)
        #pragma unroll
        for (int j = 0; j < 4; j++) acc[nt][j] = 0.f;

    const __half* pA0 = sA + (rlo + lr) * HPAD + lc * 2;
    const __half* pA1 = pA0 + 8 * HPAD;
    const int bOff = (wc * 64 + lr) * WPAD + lc * 2;

    for (int j = 0; j < K; j++) {
        if (j + 1 < K) { CP_WAIT(1); } else { CP_WAIT(0); }
        __syncthreads();

        const int seg = j >> 1;
        const int kh = j & 1;
        const int a = sRow[seg];
        const int b = sRow[seg + 1];
        const __half* pB0 = ((j & 1) ? sW1 : sW0) + bOff;

        if (b > rlo && a < rlo + 16) {
            const int r0 = rlo + lr;
            const uint32_t am0 = (r0 >= a && r0 < b) ? 0xffffffffu : 0u;
            const uint32_t am1 = (r0 + 8 >= a && r0 + 8 < b) ? 0xffffffffu : 0u;
            const __half* pAk0 = pA0 + kh * 64;
            const __half* pAk1 = pA1 + kh * 64;

            #pragma unroll
            for (int ks = 0; ks < 4; ks++) {
                const int k0 = ks * 16;
                uint32_t aF[4];
                aF[0] = *(const uint32_t*)(pAk0 + k0) & am0;
                aF[1] = *(const uint32_t*)(pAk1 + k0) & am1;
                aF[2] = *(const uint32_t*)(pAk0 + k0 + 8) & am0;
                aF[3] = *(const uint32_t*)(pAk1 + k0 + 8) & am1;
                #pragma unroll
                for (int nt = 0; nt < 8; nt++) {
                    const __half* pB = pB0 + nt * (8 * WPAD) + k0;
                    uint32_t b0 = *(const uint32_t*)(pB);
                    uint32_t b1 = *(const uint32_t*)(pB + 8);
                    mma_f16(acc[nt], aF, b0, b1);
                }
            }
        }

        __syncthreads();                 // readers done with buffer (j&1)
        if (j + 2 < K) {
            const int jn = j + 2;
            issue_w(sSpec[jn >> 1], jn & 1, jn & 1);
        }
    }

    // ---- epilogue: acc + h_prev -> out (coalesced float2, 32B sectors) ----
    #pragma unroll
    for (int h = 0; h < 2; h++) {
        const int r = R0 + rlo + 8 * h + lr;
        const float* hp = h_prev + (size_t)r * D;
        float* op = out + (size_t)r * D;
        #pragma unroll
        for (int nt = 0; nt < 8; nt++) {
            const int c = wc * 64 + 8 * nt + lc * 2;
            float2 hv = *(const float2*)(hp + c);
            float2 o;
            o.x = hv.x + acc[nt][2 * h + 0];
            o.y = hv.y + acc[nt][2 * h + 1];
            *(float2*)(op + c) = o;
        }
    }
}

extern "C" void kernel_launch(void* const* d_in, const int* in_sizes, int n_in,
                              void* d_out, int out_size) {
    const float* h_prev     = (const float*)d_in[0];
    const float* m_curr     = (const float*)d_in[1];
    const int*   atom_types = (const int*)d_in[2];
    const float* weight     = (const float*)d_in[3];
    float* out = (float*)d_out;

    int n_nodes = in_sizes[0] / D;          // 16384
    int grid = n_nodes / TILE_M;            // 256
    int wgrid = (NSPEC * D * D) / 4 / NT;   // 1904 exact

    cudaFuncSetAttribute(element_update_kernel,
                         cudaFuncAttributeMaxDynamicSharedMemorySize, SMEM_BYTES);

    convert_w<<<wgrid, NT>>>(weight);
    element_update_kernel<<<grid, NT, SMEM_BYTES>>>(h_prev, m_curr, atom_types, out);
}